// round 11
// baseline (speedup 1.0000x reference)
#include <cuda_runtime.h>
#include <cuda_bf16.h>
#include <cstdint>

// Problem constants
#define T_SEQ 512
#define B_SZ  64
#define E_SZ  512
#define G3E   1536
#define M_ROWS (T_SEQ * B_SZ)

// ---------------- device scratch ----------------
__device__ float g_x[T_SEQ * B_SZ * E_SZ];
__device__ float g_xproj[T_SEQ * B_SZ * G3E];
__device__ float g_h[B_SZ * E_SZ];
__device__ unsigned g_ctr[128];      // per-(bg,eg) counters, 8 warp-arrivals per step

// ---------------- f32x2 helpers ----------------
__device__ __forceinline__ void fma2(unsigned long long& d, unsigned long long a,
                                     unsigned long long b) {
    asm("fma.rn.f32x2 %0, %1, %2, %3;" : "=l"(d) : "l"(a), "l"(b), "l"(d));
}
__device__ __forceinline__ float f32x2_sum(unsigned long long v) {
    return __uint_as_float((unsigned)v) + __uint_as_float((unsigned)(v >> 32));
}
__device__ __forceinline__ unsigned long long dup2(float x) {
    unsigned long long r; unsigned u = __float_as_uint(x);
    asm("mov.b64 %0, {%1, %1};" : "=l"(r) : "r"(u));
    return r;
}

// ---------------- counter primitives ----------------
__device__ __forceinline__ void ctr_release_add(unsigned* ctr) {
    asm volatile("red.release.gpu.global.add.u32 [%0], %1;" :: "l"(ctr), "r"(1u) : "memory");
}
__device__ __forceinline__ void ctr_wait(unsigned* ctr, unsigned target) {
    unsigned cur;
    do {
        asm volatile("ld.acquire.gpu.u32 %0, [%1];" : "=r"(cur) : "l"(ctr) : "memory");
    } while ((int)(cur - target) < 0);
}

// ---------------- embedding gather (+ counter reset) ----------------
__global__ void embed_kernel(const int* __restrict__ idx,
                             const float* __restrict__ emb,
                             float* __restrict__ out) {
    if (blockIdx.x == 0 && threadIdx.x < 128) g_ctr[threadIdx.x] = 0u;
    int i = blockIdx.x * blockDim.x + threadIdx.x;
    const int total = T_SEQ * B_SZ * (E_SZ / 4);
    if (i >= total) return;
    int row = i >> 7;
    int col = i & 127;
    int tok = idx[row];
    reinterpret_cast<float4*>(out)[i] =
        reinterpret_cast<const float4*>(emb)[(size_t)tok * 128 + col];
}

// ---------------- fp32 GEMM: 512 threads, warp-uniform A (broadcast LDS) ----------------
// C[M,N] = A[M,K]*B[N,K]^T + bias. 128x128 tile, BK=16. Thread (tx=tid&31, ty=tid>>5)
// owns 8 rows (ty*8..+7) x 4 cols (tx*4..+3). Within a warp ty is constant ->
// A smem reads are broadcasts; B reads are phase-conflict-free float4.
#define BM 128
#define BN 128
#define BK 16

__global__ __launch_bounds__(512, 2) void gemm_nt_bias(
    const float* __restrict__ A, const float* __restrict__ Bm,
    const float* __restrict__ bias, float* __restrict__ C,
    int M, int N, int K) {
    __shared__ float As[BK][BM];
    __shared__ float Bs[BK][BN];

    const int tid = threadIdx.x;
    const int bm = blockIdx.y * BM;
    const int bn = blockIdx.x * BN;
    const int tx = tid & 31;        // 0..31 -> N cols tx*4..+3
    const int ty = tid >> 5;        // 0..15 -> M rows ty*8..+7 (warp-uniform)
    const int lrow = tid >> 2;      // 0..127 (tile loads)
    const int lkq = (tid & 3) << 2; // 0,4,8,12

    unsigned long long acc2[4][4];  // [row-pair ip][col j]
#pragma unroll
    for (int i = 0; i < 4; i++)
#pragma unroll
        for (int j = 0; j < 4; j++) acc2[i][j] = 0ULL;

    for (int k0 = 0; k0 < K; k0 += BK) {
        float4 va = *reinterpret_cast<const float4*>(&A[(size_t)(bm + lrow) * K + k0 + lkq]);
        float4 vb = *reinterpret_cast<const float4*>(&Bm[(size_t)(bn + lrow) * K + k0 + lkq]);
        As[lkq + 0][lrow] = va.x; As[lkq + 1][lrow] = va.y;
        As[lkq + 2][lrow] = va.z; As[lkq + 3][lrow] = va.w;
        Bs[lkq + 0][lrow] = vb.x; Bs[lkq + 1][lrow] = vb.y;
        Bs[lkq + 2][lrow] = vb.z; Bs[lkq + 3][lrow] = vb.w;
        __syncthreads();

#pragma unroll
        for (int k = 0; k < BK; k++) {
            ulonglong2 aq0 = *reinterpret_cast<const ulonglong2*>(&As[k][ty * 8]);
            ulonglong2 aq1 = *reinterpret_cast<const ulonglong2*>(&As[k][ty * 8 + 4]);
            float4 b0 = *reinterpret_cast<const float4*>(&Bs[k][tx * 4]);
            unsigned long long ap[4] = {aq0.x, aq0.y, aq1.x, aq1.y};
            unsigned long long bd[4] = {dup2(b0.x), dup2(b0.y), dup2(b0.z), dup2(b0.w)};
#pragma unroll
            for (int ip = 0; ip < 4; ip++)
#pragma unroll
                for (int j = 0; j < 4; j++) fma2(acc2[ip][j], ap[ip], bd[j]);
        }
        __syncthreads();
    }

    float4 bias0 = *reinterpret_cast<const float4*>(&bias[bn + tx * 4]);
    float bv[4] = {bias0.x, bias0.y, bias0.z, bias0.w};
#pragma unroll
    for (int ip = 0; ip < 4; ip++) {
        float lo[4], hi[4];
#pragma unroll
        for (int j = 0; j < 4; j++) {
            lo[j] = __uint_as_float((unsigned)acc2[ip][j]) + bv[j];
            hi[j] = __uint_as_float((unsigned)(acc2[ip][j] >> 32)) + bv[j];
        }
        int row0 = bm + ty * 8 + 2 * ip;
        float* cp0 = &C[(size_t)row0 * N + bn + tx * 4];
        float* cp1 = cp0 + N;
        *reinterpret_cast<float4*>(cp0) = make_float4(lo[0], lo[1], lo[2], lo[3]);
        *reinterpret_cast<float4*>(cp1) = make_float4(hi[0], hi[1], hi[2], hi[3]);
    }
}

// ---------------- persistent GRU recurrence (R6 base, lean sync) ----------------
// 128 CTAs = 8 bg x 16 eg, 256 threads = 8 warps. Warp w: k-slice [64w,64w+64)
// in the dot, and batch row b=w for gates/publish. Per-warp publish: STG h row
// -> syncwarp -> lane0 red.release.add (8 arrivals/step). Consumers poll to
// 8*(t+1). One-round reduce via 6144-float buffer overlapping dead h region.
#define RGRID 128
#define EGROUPS 16
#define BTILE 8
#define WROWS 96
#define WSTR 516
#define REGION_FLOATS 6144
#define RSMEM_FLOATS (WROWS * WSTR + REGION_FLOATS)
#define RSMEM_BYTES (RSMEM_FLOATS * 4)      // 222,720 B

__global__ __launch_bounds__(256, 1) void gru_recur_kernel(
    const float* __restrict__ xproj,
    const float* __restrict__ Whh,
    const float* __restrict__ bhh,
    const int* __restrict__ lens,
    float* __restrict__ hbuf,
    float* __restrict__ ybuf,
    float* __restrict__ finals,
    int epoch)
{
    extern __shared__ float smem[];
    float* sh_w = smem;                          // WROWS * WSTR
    float* sh_h = smem + WROWS * WSTR;           // 8 stripes of 512 (dot phase)
    float* sh_part = sh_h;                       // 6144-float reduce buffer (overlap)

    const int tid = threadIdx.x;
    const int cta = blockIdx.x;
    const int bg = cta / EGROUPS;
    const int eg = cta % EGROUPS;
    const int ebase = eg * 32;
    const int w = tid >> 5;              // k-slice warp AND gate batch row
    const int jg = tid & 31;
    const int bglob = bg * BTILE + w;
    const int e = ebase + jg;
    const int kbase = w * 64;

    unsigned* my_ctr = &g_ctr[cta];
    // this warp's two producer CTAs (h cols [64w,64w+32) and [64w+32,64w+64))
    unsigned* p0 = &g_ctr[bg * EGROUPS + 2 * w];
    unsigned* p1 = p0 + 1;
    unsigned* pc = (jg < 16) ? p0 : p1;          // split polling across half-warps
    const unsigned base = (unsigned)epoch * (8u * (T_SEQ + 1));

    // weight cache: row j = elocal*3 + gate, stride WSTR (conflict-free LDS.128)
    for (int idx = tid; idx < WROWS * (E_SZ / 4); idx += 256) {
        int j = idx >> 7;
        int kq = (idx & 127) << 2;
        int el = j / 3, gate = j - el * 3;
        *reinterpret_cast<float4*>(&sh_w[j * WSTR + kq]) =
            *reinterpret_cast<const float4*>(&Whh[(size_t)(gate * E_SZ + ebase + el) * E_SZ + kq]);
    }

    const float bh0 = bhh[0 * E_SZ + e];
    const float bh1 = bhh[1 * E_SZ + e];
    const float bh2 = bhh[2 * E_SZ + e];
    const int mylen = lens[bglob];

    // init: each warp zeroes its h row, publishes (counter reaches 8)
    hbuf[bglob * E_SZ + e] = 0.f;
    __syncwarp();
    if (jg == 0) ctr_release_add(my_ctr);
    __syncthreads();     // weights loaded before dot

    const float* wp0 = sh_w + (jg * 3 + 0) * WSTR;
    const float* wp1 = wp0 + WSTR;
    const float* wp2 = wp1 + WSTR;
    float* sh_hs = sh_h + w * 512;               // this warp's stripe [b][64]

    float hprev = 0.f;
    float hnew = 0.f;

    for (int t = 0; t < T_SEQ; t++) {
        // xp prefetch (independent of h; issues before the polls below)
        const float* xp = xproj + ((size_t)t * B_SZ + bglob) * G3E;
        float xr = xp[e];
        float xz = xp[E_SZ + e];
        float xn = xp[2 * E_SZ + e];

        // wait for this warp's two producer CTAs (half-warp split polling)
        ctr_wait(pc, base + 8u * (unsigned)(t + 1));
        __syncwarp();

        // stage this warp's 8x64 h slice: 4 float4 per lane
        {
            const float4* hb4 = reinterpret_cast<const float4*>(hbuf);
#pragma unroll
            for (int i = 0; i < 4; i++) {
                int f = jg + i * 32;             // 0..127
                int b = f >> 4, c4 = f & 15;
                float4 v = hb4[(bg * BTILE + b) * 128 + 16 * w + c4];
                *reinterpret_cast<float4*>(&sh_hs[b * 64 + c4 * 4]) = v;
            }
        }
        __syncwarp();

        // dot: 16 iters x 3 gates x 8 batch rows, f32x2
        unsigned long long a0[8], a1[8], a2[8];
#pragma unroll
        for (int b = 0; b < 8; b++) { a0[b] = 0ULL; a1[b] = 0ULL; a2[b] = 0ULL; }

#pragma unroll 4
        for (int kk = 0; kk < 16; kk++) {
            int k4 = kbase + kk * 4;
            int kl = kk * 4;
            ulonglong2 w0 = *reinterpret_cast<const ulonglong2*>(wp0 + k4);
            ulonglong2 w1 = *reinterpret_cast<const ulonglong2*>(wp1 + k4);
            ulonglong2 w2 = *reinterpret_cast<const ulonglong2*>(wp2 + k4);
#pragma unroll
            for (int b = 0; b < 8; b++) {
                ulonglong2 h2 = *reinterpret_cast<const ulonglong2*>(sh_hs + b * 64 + kl);
                fma2(a0[b], h2.x, w0.x); fma2(a0[b], h2.y, w0.y);
                fma2(a1[b], h2.x, w1.x); fma2(a1[b], h2.y, w1.y);
                fma2(a2[b], h2.x, w2.x); fma2(a2[b], h2.y, w2.y);
            }
        }

        __syncthreads();   // all dots done; h region dead

        // one-round partial store: part[w][gate][b][lane]
#pragma unroll
        for (int b = 0; b < 8; b++) {
            sh_part[((w * 3 + 0) * 8 + b) * 32 + jg] = f32x2_sum(a0[b]);
            sh_part[((w * 3 + 1) * 8 + b) * 32 + jg] = f32x2_sum(a1[b]);
            sh_part[((w * 3 + 2) * 8 + b) * 32 + jg] = f32x2_sum(a2[b]);
        }
        __syncthreads();

        // reduce: thread (w, jg) sums the 8 warp partials per gate for row b=w
        float s0 = 0.f, s1 = 0.f, s2 = 0.f;
#pragma unroll
        for (int ww = 0; ww < 8; ww++) {
            s0 += sh_part[((ww * 3 + 0) * 8 + w) * 32 + jg];
            s1 += sh_part[((ww * 3 + 1) * 8 + w) * 32 + jg];
            s2 += sh_part[((ww * 3 + 2) * 8 + w) * 32 + jg];
        }

        // gates (fast math)
        float hr = s0 + bh0, hz = s1 + bh1, hn = s2 + bh2;
        float r = __frcp_rn(1.f + __expf(-(xr + hr)));
        float z = __frcp_rn(1.f + __expf(-(xz + hz)));
        float te = __expf(2.f * (xn + r * hn));
        float n = (te - 1.f) * __frcp_rn(te + 1.f);
        bool m = (t < mylen);
        hnew = m ? ((1.f - z) * n + z * hprev) : hprev;
        hprev = hnew;

        // per-warp publish: this warp fully owns batch row b=w
        hbuf[bglob * E_SZ + e] = hnew;
        __syncwarp();
        if (jg == 0) ctr_release_add(my_ctr);

        ybuf[((size_t)t * B_SZ + bglob) * E_SZ + e] = m ? hnew : 0.f;

        __syncthreads();   // reduce-reads done before next iter's stage overwrites
    }

    finals[bglob * E_SZ + e] = hnew;
}

// ---------------- launch ----------------
extern "C" void kernel_launch(void* const* d_in, const int* in_sizes, int n_in,
                              void* d_out, int out_size) {
    const int*   input_batch = (const int*)d_in[0];
    const int*   lens        = (const int*)d_in[1];
    const float* emb         = (const float*)d_in[2];
    const float* W_ih        = (const float*)d_in[3];
    const float* W_hh        = (const float*)d_in[4];
    const float* b_ih        = (const float*)d_in[5];
    const float* b_hh        = (const float*)d_in[6];
    float* out = (float*)d_out;

    void* p;
    cudaGetSymbolAddress(&p, g_x);     float* gx  = (float*)p;
    cudaGetSymbolAddress(&p, g_xproj); float* gxp = (float*)p;
    cudaGetSymbolAddress(&p, g_h);     float* gh  = (float*)p;

    cudaFuncSetAttribute(gru_recur_kernel,
                         cudaFuncAttributeMaxDynamicSharedMemorySize, RSMEM_BYTES);

    const int M = M_ROWS;
    const size_t out_x_elems = (size_t)T_SEQ * B_SZ * E_SZ;
    float* finals0 = out + out_x_elems;
    float* finals1 = out + out_x_elems + B_SZ * E_SZ;

    {
        int total = T_SEQ * B_SZ * (E_SZ / 4);
        embed_kernel<<<(total + 255) / 256, 256>>>(input_batch, emb, gx);
    }
    gemm_nt_bias<<<dim3(G3E / BN, M / BM), 512>>>(gx, W_ih, b_ih, gxp, M, G3E, E_SZ);
    gru_recur_kernel<<<RGRID, 256, RSMEM_BYTES>>>(gxp, W_hh, b_hh, lens, gh, gx, finals0, 0);
    gemm_nt_bias<<<dim3(G3E / BN, M / BM), 512>>>(gx, W_ih + (size_t)G3E * E_SZ,
                                                  b_ih + G3E, gxp, M, G3E, E_SZ);
    gru_recur_kernel<<<RGRID, 256, RSMEM_BYTES>>>(gxp, W_hh + (size_t)G3E * E_SZ,
                                                  b_hh + G3E, lens, gh, out, finals1, 1);
}

// round 12
// speedup vs baseline: 1.2412x; 1.2412x over previous
#include <cuda_runtime.h>
#include <cuda_bf16.h>
#include <cstdint>

// Problem constants
#define T_SEQ 512
#define B_SZ  64
#define E_SZ  512
#define G3E   1536
#define M_ROWS (T_SEQ * B_SZ)

// ---------------- device scratch ----------------
__device__ float g_x[T_SEQ * B_SZ * E_SZ];
__device__ float g_xproj[T_SEQ * B_SZ * G3E];
__device__ float g_h[B_SZ * E_SZ];
__device__ unsigned g_step[128];     // per-(bg,eg) monotonic progress counters

// ---------------- f32x2 helpers ----------------
__device__ __forceinline__ void fma2(unsigned long long& d, unsigned long long a,
                                     unsigned long long b) {
    asm("fma.rn.f32x2 %0, %1, %2, %3;" : "=l"(d) : "l"(a), "l"(b), "l"(d));
}
__device__ __forceinline__ float f32x2_sum(unsigned long long v) {
    return __uint_as_float((unsigned)v) + __uint_as_float((unsigned)(v >> 32));
}
__device__ __forceinline__ unsigned long long dup2(float x) {
    unsigned long long r; unsigned u = __float_as_uint(x);
    asm("mov.b64 %0, {%1, %1};" : "=l"(r) : "r"(u));
    return r;
}

// ---------------- counter primitives ----------------
__device__ __forceinline__ void ctr_release_add(unsigned* ctr) {
    asm volatile("red.release.gpu.global.add.u32 [%0], %1;" :: "l"(ctr), "r"(1u) : "memory");
}
__device__ __forceinline__ void ctr_wait(unsigned* ctr, unsigned target) {
    unsigned cur;
    do {
        asm volatile("ld.acquire.gpu.u32 %0, [%1];" : "=r"(cur) : "l"(ctr) : "memory");
    } while ((int)(cur - target) < 0);
}

// ---------------- embedding gather (+ counter reset) ----------------
__global__ void embed_kernel(const int* __restrict__ idx,
                             const float* __restrict__ emb,
                             float* __restrict__ out) {
    if (blockIdx.x == 0 && threadIdx.x < 128) g_step[threadIdx.x] = 0u;
    int i = blockIdx.x * blockDim.x + threadIdx.x;
    const int total = T_SEQ * B_SZ * (E_SZ / 4);
    if (i >= total) return;
    int row = i >> 7;
    int col = i & 127;
    int tok = idx[row];
    reinterpret_cast<float4*>(out)[i] =
        reinterpret_cast<const float4*>(emb)[(size_t)tok * 128 + col];
}

// ---------------- fp32 GEMM: 512 thr, warp-uniform A, pre-duplicated B ----------------
// C[M,N] = A[M,K]*B[N,K]^T + bias. 128x128 tile, BK=16.
// Thread (tx=tid&31, ty=tid>>5) owns rows ty*8..+7, cols {2tx,2tx+1,64+2tx,64+2tx+1}.
// A reads are warp-broadcast LDS.128; B reads are conflict-free LDS.128 of
// pre-duplicated f32x2 pairs (no per-use dup MOVs).
#define BM 128
#define BN 128
#define BK 16
#define ASTR 132          // As row stride (pad: 2-phase stores)
#define BSTR 130          // Bsd row stride in u64 (16B-aligned rows, reduced store conflicts)

__global__ __launch_bounds__(512, 2) void gemm_nt_bias(
    const float* __restrict__ A, const float* __restrict__ Bm,
    const float* __restrict__ bias, float* __restrict__ C,
    int M, int N, int K) {
    __shared__ float As[BK * ASTR];                  // 8448 B
    __shared__ unsigned long long Bsd[BK * BSTR];    // 16640 B

    const int tid = threadIdx.x;
    const int bm = blockIdx.y * BM;
    const int bn = blockIdx.x * BN;
    const int tx = tid & 31;        // 0..31
    const int ty = tid >> 5;        // 0..15 (warp-uniform)
    const int lrow = tid >> 2;      // 0..127 (tile loads)
    const int lkq = (tid & 3) << 2; // 0,4,8,12

    unsigned long long acc2[4][4];  // [row-pair ip][col j]
#pragma unroll
    for (int i = 0; i < 4; i++)
#pragma unroll
        for (int j = 0; j < 4; j++) acc2[i][j] = 0ULL;

    for (int k0 = 0; k0 < K; k0 += BK) {
        float4 va = *reinterpret_cast<const float4*>(&A[(size_t)(bm + lrow) * K + k0 + lkq]);
        float4 vb = *reinterpret_cast<const float4*>(&Bm[(size_t)(bn + lrow) * K + k0 + lkq]);
        As[(lkq + 0) * ASTR + lrow] = va.x; As[(lkq + 1) * ASTR + lrow] = va.y;
        As[(lkq + 2) * ASTR + lrow] = va.z; As[(lkq + 3) * ASTR + lrow] = va.w;
        Bsd[(lkq + 0) * BSTR + lrow] = dup2(vb.x); Bsd[(lkq + 1) * BSTR + lrow] = dup2(vb.y);
        Bsd[(lkq + 2) * BSTR + lrow] = dup2(vb.z); Bsd[(lkq + 3) * BSTR + lrow] = dup2(vb.w);
        __syncthreads();

#pragma unroll
        for (int k = 0; k < BK; k++) {
            ulonglong2 aq0 = *reinterpret_cast<const ulonglong2*>(&As[k * ASTR + ty * 8]);
            ulonglong2 aq1 = *reinterpret_cast<const ulonglong2*>(&As[k * ASTR + ty * 8 + 4]);
            ulonglong2 bq0 = *reinterpret_cast<const ulonglong2*>(&Bsd[k * BSTR + 2 * tx]);
            ulonglong2 bq1 = *reinterpret_cast<const ulonglong2*>(&Bsd[k * BSTR + 64 + 2 * tx]);
            unsigned long long ap[4] = {aq0.x, aq0.y, aq1.x, aq1.y};
            unsigned long long bd[4] = {bq0.x, bq0.y, bq1.x, bq1.y};
#pragma unroll
            for (int ip = 0; ip < 4; ip++)
#pragma unroll
                for (int j = 0; j < 4; j++) fma2(acc2[ip][j], ap[ip], bd[j]);
        }
        __syncthreads();
    }

    // bias for cols 2tx, 2tx+1, 64+2tx, 64+2tx+1
    float2 bias0 = *reinterpret_cast<const float2*>(&bias[bn + 2 * tx]);
    float2 bias1 = *reinterpret_cast<const float2*>(&bias[bn + 64 + 2 * tx]);
    float bv[4] = {bias0.x, bias0.y, bias1.x, bias1.y};
#pragma unroll
    for (int ip = 0; ip < 4; ip++) {
        float lo[4], hi[4];
#pragma unroll
        for (int j = 0; j < 4; j++) {
            lo[j] = __uint_as_float((unsigned)acc2[ip][j]) + bv[j];
            hi[j] = __uint_as_float((unsigned)(acc2[ip][j] >> 32)) + bv[j];
        }
        int row0 = bm + ty * 8 + 2 * ip;
        float* cp0 = &C[(size_t)row0 * N + bn];
        float* cp1 = cp0 + N;
        *reinterpret_cast<float2*>(cp0 + 2 * tx)      = make_float2(lo[0], lo[1]);
        *reinterpret_cast<float2*>(cp0 + 64 + 2 * tx) = make_float2(lo[2], lo[3]);
        *reinterpret_cast<float2*>(cp1 + 2 * tx)      = make_float2(hi[0], hi[1]);
        *reinterpret_cast<float2*>(cp1 + 64 + 2 * tx) = make_float2(hi[2], hi[3]);
    }
}

// ---------------- persistent GRU recurrence (exact R6 + one-round reduce) ----------------
// 128 CTAs = 8 bg x 16 eg, 256 threads = 8 warps.
// Per-(bg,eg) counters, ONE CTA-wide publish per step (tid0, after syncthreads).
// Warp w: k-slice [64w,64w+64) in the dot, batch row b=w for gates.
// One-round reduce through 6144-float buffer overlapping the dead h region.
#define RGRID 128
#define EGROUPS 16
#define BTILE 8
#define WROWS 96
#define WSTR 516
#define REGION_FLOATS 6144
#define RSMEM_FLOATS (WROWS * WSTR + REGION_FLOATS)
#define RSMEM_BYTES (RSMEM_FLOATS * 4)      // 222,720 B

__global__ __launch_bounds__(256, 1) void gru_recur_kernel(
    const float* __restrict__ xproj,
    const float* __restrict__ Whh,
    const float* __restrict__ bhh,
    const int* __restrict__ lens,
    float* __restrict__ hbuf,
    float* __restrict__ ybuf,
    float* __restrict__ finals,
    int epoch)
{
    extern __shared__ float smem[];
    float* sh_w = smem;                          // WROWS * WSTR
    float* sh_h = smem + WROWS * WSTR;           // 8 stripes of 512 (dot phase)
    float* sh_part = sh_h;                       // 6144-float reduce buffer (overlap)

    const int tid = threadIdx.x;
    const int cta = blockIdx.x;
    const int bg = cta / EGROUPS;
    const int eg = cta % EGROUPS;
    const int ebase = eg * 32;
    const int w = tid >> 5;              // k-slice warp AND gate batch row
    const int jg = tid & 31;
    const int bglob = bg * BTILE + w;
    const int e = ebase + jg;
    const int kbase = w * 64;

    unsigned* my_ctr = &g_step[cta];
    unsigned* p0 = &g_step[bg * EGROUPS + 2 * w];
    unsigned* p1 = p0 + 1;
    const unsigned tgt0 = (unsigned)epoch * (T_SEQ + 1) + 1u;

    // weight cache: row j = elocal*3 + gate, stride WSTR (conflict-free LDS.128)
    for (int idx = tid; idx < WROWS * (E_SZ / 4); idx += 256) {
        int j = idx >> 7;
        int kq = (idx & 127) << 2;
        int el = j / 3, gate = j - el * 3;
        *reinterpret_cast<float4*>(&sh_w[j * WSTR + kq]) =
            *reinterpret_cast<const float4*>(&Whh[(size_t)(gate * E_SZ + ebase + el) * E_SZ + kq]);
    }

    const float bh0 = bhh[0 * E_SZ + e];
    const float bh1 = bhh[1 * E_SZ + e];
    const float bh2 = bhh[2 * E_SZ + e];
    const int mylen = lens[bglob];

    // init: zero our slice of h, publish
    hbuf[bglob * E_SZ + e] = 0.f;
    __syncthreads();
    if (tid == 0) ctr_release_add(my_ctr);

    const float* wp0 = sh_w + (jg * 3 + 0) * WSTR;
    const float* wp1 = wp0 + WSTR;
    const float* wp2 = wp1 + WSTR;
    float* sh_hs = sh_h + w * 512;               // this warp's stripe: [b][64]

    float hprev = 0.f;
    float hnew = 0.f;

    for (int t = 0; t < T_SEQ; t++) {
        // xp prefetch (independent of h)
        const float* xp = xproj + ((size_t)t * B_SZ + bglob) * G3E;
        float xr = xp[e];
        float xz = xp[E_SZ + e];
        float xn = xp[2 * E_SZ + e];

        // wait for this warp's two producer CTAs
        ctr_wait(p0, tgt0 + (unsigned)t);
        ctr_wait(p1, tgt0 + (unsigned)t);

        // stage this warp's 8x64 h slice: 4 float4 per lane
        {
            const float4* hb4 = reinterpret_cast<const float4*>(hbuf);
#pragma unroll
            for (int i = 0; i < 4; i++) {
                int f = jg + i * 32;             // 0..127
                int b = f >> 4, c4 = f & 15;
                float4 v = hb4[(bg * BTILE + b) * 128 + 16 * w + c4];
                *reinterpret_cast<float4*>(&sh_hs[b * 64 + c4 * 4]) = v;
            }
        }
        __syncwarp();

        // dot: 16 iters x 3 gates x 8 batch rows, f32x2
        unsigned long long a0[8], a1[8], a2[8];
#pragma unroll
        for (int b = 0; b < 8; b++) { a0[b] = 0ULL; a1[b] = 0ULL; a2[b] = 0ULL; }

#pragma unroll 4
        for (int kk = 0; kk < 16; kk++) {
            int k4 = kbase + kk * 4;
            int kl = kk * 4;
            ulonglong2 w0 = *reinterpret_cast<const ulonglong2*>(wp0 + k4);
            ulonglong2 w1 = *reinterpret_cast<const ulonglong2*>(wp1 + k4);
            ulonglong2 w2 = *reinterpret_cast<const ulonglong2*>(wp2 + k4);
#pragma unroll
            for (int b = 0; b < 8; b++) {
                ulonglong2 h2 = *reinterpret_cast<const ulonglong2*>(sh_hs + b * 64 + kl);
                fma2(a0[b], h2.x, w0.x); fma2(a0[b], h2.y, w0.y);
                fma2(a1[b], h2.x, w1.x); fma2(a1[b], h2.y, w1.y);
                fma2(a2[b], h2.x, w2.x); fma2(a2[b], h2.y, w2.y);
            }
        }

        __syncthreads();   // all dots done; h region dead

        // one-round partial store: part[w][gate][b][lane]
#pragma unroll
        for (int b = 0; b < 8; b++) {
            sh_part[((w * 3 + 0) * 8 + b) * 32 + jg] = f32x2_sum(a0[b]);
            sh_part[((w * 3 + 1) * 8 + b) * 32 + jg] = f32x2_sum(a1[b]);
            sh_part[((w * 3 + 2) * 8 + b) * 32 + jg] = f32x2_sum(a2[b]);
        }
        __syncthreads();

        // reduce: thread (w, jg) sums 8 warp partials per gate for row b=w
        float s0 = 0.f, s1 = 0.f, s2 = 0.f;
#pragma unroll
        for (int ww = 0; ww < 8; ww++) {
            s0 += sh_part[((ww * 3 + 0) * 8 + w) * 32 + jg];
            s1 += sh_part[((ww * 3 + 1) * 8 + w) * 32 + jg];
            s2 += sh_part[((ww * 3 + 2) * 8 + w) * 32 + jg];
        }

        // gates (fast math)
        float hr = s0 + bh0, hz = s1 + bh1, hn = s2 + bh2;
        float r = __frcp_rn(1.f + __expf(-(xr + hr)));
        float z = __frcp_rn(1.f + __expf(-(xz + hz)));
        float te = __expf(2.f * (xn + r * hn));
        float n = (te - 1.f) * __frcp_rn(te + 1.f);
        bool m = (t < mylen);
        hnew = m ? ((1.f - z) * n + z * hprev) : hprev;
        hprev = hnew;

        // CTA-wide publish (R6 protocol): store h, barrier, single release-add
        hbuf[bglob * E_SZ + e] = hnew;
        __syncthreads();                 // h stores done AND sh_part reads done
        if (tid == 0) ctr_release_add(my_ctr);

        ybuf[((size_t)t * B_SZ + bglob) * E_SZ + e] = m ? hnew : 0.f;
    }

    finals[bglob * E_SZ + e] = hnew;
}

// ---------------- launch ----------------
extern "C" void kernel_launch(void* const* d_in, const int* in_sizes, int n_in,
                              void* d_out, int out_size) {
    const int*   input_batch = (const int*)d_in[0];
    const int*   lens        = (const int*)d_in[1];
    const float* emb         = (const float*)d_in[2];
    const float* W_ih        = (const float*)d_in[3];
    const float* W_hh        = (const float*)d_in[4];
    const float* b_ih        = (const float*)d_in[5];
    const float* b_hh        = (const float*)d_in[6];
    float* out = (float*)d_out;

    void* p;
    cudaGetSymbolAddress(&p, g_x);     float* gx  = (float*)p;
    cudaGetSymbolAddress(&p, g_xproj); float* gxp = (float*)p;
    cudaGetSymbolAddress(&p, g_h);     float* gh  = (float*)p;

    cudaFuncSetAttribute(gru_recur_kernel,
                         cudaFuncAttributeMaxDynamicSharedMemorySize, RSMEM_BYTES);

    const int M = M_ROWS;
    const size_t out_x_elems = (size_t)T_SEQ * B_SZ * E_SZ;
    float* finals0 = out + out_x_elems;
    float* finals1 = out + out_x_elems + B_SZ * E_SZ;

    {
        int total = T_SEQ * B_SZ * (E_SZ / 4);
        embed_kernel<<<(total + 255) / 256, 256>>>(input_batch, emb, gx);
    }
    gemm_nt_bias<<<dim3(G3E / BN, M / BM), 512>>>(gx, W_ih, b_ih, gxp, M, G3E, E_SZ);
    gru_recur_kernel<<<RGRID, 256, RSMEM_BYTES>>>(gxp, W_hh, b_hh, lens, gh, gx, finals0, 0);
    gemm_nt_bias<<<dim3(G3E / BN, M / BM), 512>>>(gx, W_ih + (size_t)G3E * E_SZ,
                                                  b_ih + G3E, gxp, M, G3E, E_SZ);
    gru_recur_kernel<<<RGRID, 256, RSMEM_BYTES>>>(gxp, W_hh + (size_t)G3E * E_SZ,
                                                  b_hh + G3E, lens, gh, out, finals1, 1);
}

// round 13
// speedup vs baseline: 1.3137x; 1.0584x over previous
#include <cuda_runtime.h>
#include <cuda_bf16.h>
#include <cstdint>

// Problem constants
#define T_SEQ 512
#define B_SZ  64
#define E_SZ  512
#define G3E   1536
#define M_ROWS (T_SEQ * B_SZ)

// ---------------- device scratch ----------------
__device__ float g_x[T_SEQ * B_SZ * E_SZ];
__device__ float g_xproj[T_SEQ * B_SZ * G3E];
__device__ float g_h[B_SZ * E_SZ];
__device__ unsigned g_step[128];     // per-(bg,eg) monotonic progress counters

// ---------------- f32x2 helpers ----------------
__device__ __forceinline__ void fma2(unsigned long long& d, unsigned long long a,
                                     unsigned long long b) {
    asm("fma.rn.f32x2 %0, %1, %2, %3;" : "=l"(d) : "l"(a), "l"(b), "l"(d));
}
__device__ __forceinline__ float f32x2_sum(unsigned long long v) {
    return __uint_as_float((unsigned)v) + __uint_as_float((unsigned)(v >> 32));
}
__device__ __forceinline__ unsigned long long dup2(float x) {
    unsigned long long r; unsigned u = __float_as_uint(x);
    asm("mov.b64 %0, {%1, %1};" : "=l"(r) : "r"(u));
    return r;
}

// ---------------- counter primitives ----------------
__device__ __forceinline__ void ctr_release_add(unsigned* ctr) {
    asm volatile("red.release.gpu.global.add.u32 [%0], %1;" :: "l"(ctr), "r"(1u) : "memory");
}
__device__ __forceinline__ void ctr_wait(unsigned* ctr, unsigned target) {
    unsigned cur;
    do {
        asm volatile("ld.acquire.gpu.u32 %0, [%1];" : "=r"(cur) : "l"(ctr) : "memory");
    } while ((int)(cur - target) < 0);
}

// ---------------- embedding gather (+ counter reset) ----------------
__global__ void embed_kernel(const int* __restrict__ idx,
                             const float* __restrict__ emb,
                             float* __restrict__ out) {
    if (blockIdx.x == 0 && threadIdx.x < 128) g_step[threadIdx.x] = 0u;
    int i = blockIdx.x * blockDim.x + threadIdx.x;
    const int total = T_SEQ * B_SZ * (E_SZ / 4);
    if (i >= total) return;
    int row = i >> 7;
    int col = i & 127;
    int tok = idx[row];
    reinterpret_cast<float4*>(out)[i] =
        reinterpret_cast<const float4*>(emb)[(size_t)tok * 128 + col];
}

// ---------------- fp32 GEMM (exact R11): 512 thr, warp-uniform A broadcasts ----------------
// C[M,N] = A[M,K]*B[N,K]^T + bias. 128x128 tile, BK=16. Thread (tx=tid&31, ty=tid>>5)
// owns 8 rows (ty*8..+7) x 4 cols (tx*4..+3). Within a warp ty is constant ->
// A smem reads are broadcasts; B reads are phase-conflict-free float4.
#define BM 128
#define BN 128
#define BK 16

__global__ __launch_bounds__(512, 2) void gemm_nt_bias(
    const float* __restrict__ A, const float* __restrict__ Bm,
    const float* __restrict__ bias, float* __restrict__ C,
    int M, int N, int K) {
    __shared__ float As[BK][BM];
    __shared__ float Bs[BK][BN];

    const int tid = threadIdx.x;
    const int bm = blockIdx.y * BM;
    const int bn = blockIdx.x * BN;
    const int tx = tid & 31;        // 0..31 -> N cols tx*4..+3
    const int ty = tid >> 5;        // 0..15 -> M rows ty*8..+7 (warp-uniform)
    const int lrow = tid >> 2;      // 0..127 (tile loads)
    const int lkq = (tid & 3) << 2; // 0,4,8,12

    unsigned long long acc2[4][4];  // [row-pair ip][col j]
#pragma unroll
    for (int i = 0; i < 4; i++)
#pragma unroll
        for (int j = 0; j < 4; j++) acc2[i][j] = 0ULL;

    for (int k0 = 0; k0 < K; k0 += BK) {
        float4 va = *reinterpret_cast<const float4*>(&A[(size_t)(bm + lrow) * K + k0 + lkq]);
        float4 vb = *reinterpret_cast<const float4*>(&Bm[(size_t)(bn + lrow) * K + k0 + lkq]);
        As[lkq + 0][lrow] = va.x; As[lkq + 1][lrow] = va.y;
        As[lkq + 2][lrow] = va.z; As[lkq + 3][lrow] = va.w;
        Bs[lkq + 0][lrow] = vb.x; Bs[lkq + 1][lrow] = vb.y;
        Bs[lkq + 2][lrow] = vb.z; Bs[lkq + 3][lrow] = vb.w;
        __syncthreads();

#pragma unroll
        for (int k = 0; k < BK; k++) {
            ulonglong2 aq0 = *reinterpret_cast<const ulonglong2*>(&As[k][ty * 8]);
            ulonglong2 aq1 = *reinterpret_cast<const ulonglong2*>(&As[k][ty * 8 + 4]);
            float4 b0 = *reinterpret_cast<const float4*>(&Bs[k][tx * 4]);
            unsigned long long ap[4] = {aq0.x, aq0.y, aq1.x, aq1.y};
            unsigned long long bd[4] = {dup2(b0.x), dup2(b0.y), dup2(b0.z), dup2(b0.w)};
#pragma unroll
            for (int ip = 0; ip < 4; ip++)
#pragma unroll
                for (int j = 0; j < 4; j++) fma2(acc2[ip][j], ap[ip], bd[j]);
        }
        __syncthreads();
    }

    float4 bias0 = *reinterpret_cast<const float4*>(&bias[bn + tx * 4]);
    float bv[4] = {bias0.x, bias0.y, bias0.z, bias0.w};
#pragma unroll
    for (int ip = 0; ip < 4; ip++) {
        float lo[4], hi[4];
#pragma unroll
        for (int j = 0; j < 4; j++) {
            lo[j] = __uint_as_float((unsigned)acc2[ip][j]) + bv[j];
            hi[j] = __uint_as_float((unsigned)(acc2[ip][j] >> 32)) + bv[j];
        }
        int row0 = bm + ty * 8 + 2 * ip;
        float* cp0 = &C[(size_t)row0 * N + bn + tx * 4];
        float* cp1 = cp0 + N;
        *reinterpret_cast<float4*>(cp0) = make_float4(lo[0], lo[1], lo[2], lo[3]);
        *reinterpret_cast<float4*>(cp1) = make_float4(hi[0], hi[1], hi[2], hi[3]);
    }
}

// ---------------- persistent GRU recurrence (exact R12) ----------------
// 128 CTAs = 8 bg x 16 eg, 256 threads = 8 warps.
// Per-(bg,eg) counters, ONE CTA-wide publish per step (tid0, after syncthreads).
// Warp w: k-slice [64w,64w+64) in the dot, batch row b=w for gates.
// One-round reduce through 6144-float buffer overlapping the dead h region.
#define RGRID 128
#define EGROUPS 16
#define BTILE 8
#define WROWS 96
#define WSTR 516
#define REGION_FLOATS 6144
#define RSMEM_FLOATS (WROWS * WSTR + REGION_FLOATS)
#define RSMEM_BYTES (RSMEM_FLOATS * 4)      // 222,720 B

__global__ __launch_bounds__(256, 1) void gru_recur_kernel(
    const float* __restrict__ xproj,
    const float* __restrict__ Whh,
    const float* __restrict__ bhh,
    const int* __restrict__ lens,
    float* __restrict__ hbuf,
    float* __restrict__ ybuf,
    float* __restrict__ finals,
    int epoch)
{
    extern __shared__ float smem[];
    float* sh_w = smem;                          // WROWS * WSTR
    float* sh_h = smem + WROWS * WSTR;           // 8 stripes of 512 (dot phase)
    float* sh_part = sh_h;                       // 6144-float reduce buffer (overlap)

    const int tid = threadIdx.x;
    const int cta = blockIdx.x;
    const int bg = cta / EGROUPS;
    const int eg = cta % EGROUPS;
    const int ebase = eg * 32;
    const int w = tid >> 5;              // k-slice warp AND gate batch row
    const int jg = tid & 31;
    const int bglob = bg * BTILE + w;
    const int e = ebase + jg;
    const int kbase = w * 64;

    unsigned* my_ctr = &g_step[cta];
    unsigned* p0 = &g_step[bg * EGROUPS + 2 * w];
    unsigned* p1 = p0 + 1;
    const unsigned tgt0 = (unsigned)epoch * (T_SEQ + 1) + 1u;

    // weight cache: row j = elocal*3 + gate, stride WSTR (conflict-free LDS.128)
    for (int idx = tid; idx < WROWS * (E_SZ / 4); idx += 256) {
        int j = idx >> 7;
        int kq = (idx & 127) << 2;
        int el = j / 3, gate = j - el * 3;
        *reinterpret_cast<float4*>(&sh_w[j * WSTR + kq]) =
            *reinterpret_cast<const float4*>(&Whh[(size_t)(gate * E_SZ + ebase + el) * E_SZ + kq]);
    }

    const float bh0 = bhh[0 * E_SZ + e];
    const float bh1 = bhh[1 * E_SZ + e];
    const float bh2 = bhh[2 * E_SZ + e];
    const int mylen = lens[bglob];

    // init: zero our slice of h, publish
    hbuf[bglob * E_SZ + e] = 0.f;
    __syncthreads();
    if (tid == 0) ctr_release_add(my_ctr);

    const float* wp0 = sh_w + (jg * 3 + 0) * WSTR;
    const float* wp1 = wp0 + WSTR;
    const float* wp2 = wp1 + WSTR;
    float* sh_hs = sh_h + w * 512;               // this warp's stripe: [b][64]

    float hprev = 0.f;
    float hnew = 0.f;

    for (int t = 0; t < T_SEQ; t++) {
        // xp prefetch (independent of h)
        const float* xp = xproj + ((size_t)t * B_SZ + bglob) * G3E;
        float xr = xp[e];
        float xz = xp[E_SZ + e];
        float xn = xp[2 * E_SZ + e];

        // wait for this warp's two producer CTAs
        ctr_wait(p0, tgt0 + (unsigned)t);
        ctr_wait(p1, tgt0 + (unsigned)t);

        // stage this warp's 8x64 h slice: 4 float4 per lane
        {
            const float4* hb4 = reinterpret_cast<const float4*>(hbuf);
#pragma unroll
            for (int i = 0; i < 4; i++) {
                int f = jg + i * 32;             // 0..127
                int b = f >> 4, c4 = f & 15;
                float4 v = hb4[(bg * BTILE + b) * 128 + 16 * w + c4];
                *reinterpret_cast<float4*>(&sh_hs[b * 64 + c4 * 4]) = v;
            }
        }
        __syncwarp();

        // dot: 16 iters x 3 gates x 8 batch rows, f32x2
        unsigned long long a0[8], a1[8], a2[8];
#pragma unroll
        for (int b = 0; b < 8; b++) { a0[b] = 0ULL; a1[b] = 0ULL; a2[b] = 0ULL; }

#pragma unroll 4
        for (int kk = 0; kk < 16; kk++) {
            int k4 = kbase + kk * 4;
            int kl = kk * 4;
            ulonglong2 w0 = *reinterpret_cast<const ulonglong2*>(wp0 + k4);
            ulonglong2 w1 = *reinterpret_cast<const ulonglong2*>(wp1 + k4);
            ulonglong2 w2 = *reinterpret_cast<const ulonglong2*>(wp2 + k4);
#pragma unroll
            for (int b = 0; b < 8; b++) {
                ulonglong2 h2 = *reinterpret_cast<const ulonglong2*>(sh_hs + b * 64 + kl);
                fma2(a0[b], h2.x, w0.x); fma2(a0[b], h2.y, w0.y);
                fma2(a1[b], h2.x, w1.x); fma2(a1[b], h2.y, w1.y);
                fma2(a2[b], h2.x, w2.x); fma2(a2[b], h2.y, w2.y);
            }
        }

        __syncthreads();   // all dots done; h region dead

        // one-round partial store: part[w][gate][b][lane]
#pragma unroll
        for (int b = 0; b < 8; b++) {
            sh_part[((w * 3 + 0) * 8 + b) * 32 + jg] = f32x2_sum(a0[b]);
            sh_part[((w * 3 + 1) * 8 + b) * 32 + jg] = f32x2_sum(a1[b]);
            sh_part[((w * 3 + 2) * 8 + b) * 32 + jg] = f32x2_sum(a2[b]);
        }
        __syncthreads();

        // reduce: thread (w, jg) sums 8 warp partials per gate for row b=w
        float s0 = 0.f, s1 = 0.f, s2 = 0.f;
#pragma unroll
        for (int ww = 0; ww < 8; ww++) {
            s0 += sh_part[((ww * 3 + 0) * 8 + w) * 32 + jg];
            s1 += sh_part[((ww * 3 + 1) * 8 + w) * 32 + jg];
            s2 += sh_part[((ww * 3 + 2) * 8 + w) * 32 + jg];
        }

        // gates (fast math)
        float hr = s0 + bh0, hz = s1 + bh1, hn = s2 + bh2;
        float r = __frcp_rn(1.f + __expf(-(xr + hr)));
        float z = __frcp_rn(1.f + __expf(-(xz + hz)));
        float te = __expf(2.f * (xn + r * hn));
        float n = (te - 1.f) * __frcp_rn(te + 1.f);
        bool m = (t < mylen);
        hnew = m ? ((1.f - z) * n + z * hprev) : hprev;
        hprev = hnew;

        // CTA-wide publish (R6 protocol): store h, barrier, single release-add
        hbuf[bglob * E_SZ + e] = hnew;
        __syncthreads();                 // h stores done AND sh_part reads done
        if (tid == 0) ctr_release_add(my_ctr);

        ybuf[((size_t)t * B_SZ + bglob) * E_SZ + e] = m ? hnew : 0.f;
    }

    finals[bglob * E_SZ + e] = hnew;
}

// ---------------- launch ----------------
extern "C" void kernel_launch(void* const* d_in, const int* in_sizes, int n_in,
                              void* d_out, int out_size) {
    const int*   input_batch = (const int*)d_in[0];
    const int*   lens        = (const int*)d_in[1];
    const float* emb         = (const float*)d_in[2];
    const float* W_ih        = (const float*)d_in[3];
    const float* W_hh        = (const float*)d_in[4];
    const float* b_ih        = (const float*)d_in[5];
    const float* b_hh        = (const float*)d_in[6];
    float* out = (float*)d_out;

    void* p;
    cudaGetSymbolAddress(&p, g_x);     float* gx  = (float*)p;
    cudaGetSymbolAddress(&p, g_xproj); float* gxp = (float*)p;
    cudaGetSymbolAddress(&p, g_h);     float* gh  = (float*)p;

    cudaFuncSetAttribute(gru_recur_kernel,
                         cudaFuncAttributeMaxDynamicSharedMemorySize, RSMEM_BYTES);

    const int M = M_ROWS;
    const size_t out_x_elems = (size_t)T_SEQ * B_SZ * E_SZ;
    float* finals0 = out + out_x_elems;
    float* finals1 = out + out_x_elems + B_SZ * E_SZ;

    {
        int total = T_SEQ * B_SZ * (E_SZ / 4);
        embed_kernel<<<(total + 255) / 256, 256>>>(input_batch, emb, gx);
    }
    gemm_nt_bias<<<dim3(G3E / BN, M / BM), 512>>>(gx, W_ih, b_ih, gxp, M, G3E, E_SZ);
    gru_recur_kernel<<<RGRID, 256, RSMEM_BYTES>>>(gxp, W_hh, b_hh, lens, gh, gx, finals0, 0);
    gemm_nt_bias<<<dim3(G3E / BN, M / BM), 512>>>(gx, W_ih + (size_t)G3E * E_SZ,
                                                  b_ih + G3E, gxp, M, G3E, E_SZ);
    gru_recur_kernel<<<RGRID, 256, RSMEM_BYTES>>>(gxp, W_hh + (size_t)G3E * E_SZ,
                                                  b_hh + G3E, lens, gh, out, finals1, 1);
}